// round 16
// baseline (speedup 1.0000x reference)
#include <cuda_runtime.h>
#include <cuda_fp16.h>
#include <math.h>
#include <stdint.h>

// Problem dims (fixed by the dataset)
#define B_   256
#define T_   256
#define D_   128
#define H_   512
#define G3H  1536
#define BT   (B_ * T_)

// ---------------------------------------------------------------------------
// Scratch (static device allocations; harness forbids cudaMalloc)
// ---------------------------------------------------------------------------
__device__ float g_xg[(size_t)BT * G3H];   // xg0 (layer-0 input projections)
__device__ float g_hT[B_ * H_];            // final hidden of layer 1
// h fragments, A-layout, fp16 single, 4-deep buffered (WAR safety with
// dataflow sync: write buf (t+1)&3, read buf t&3)
__device__ uint4 g_h0frag[4][16 * 32 * 32];
__device__ uint4 g_h1frag[4][16 * 32 * 32];

// Dataflow flags: one 128B line per block; monotonic gens. Each block
// publishes init + one gen per window (258 per launch) -> snapshots agree
// across blocks and graph replays.
__device__ volatile unsigned g_slot[4][32][32];

// ---------------------------------------------------------------------------
// math helpers
// ---------------------------------------------------------------------------
__device__ __forceinline__ uint32_t f2tf(float f) {
    uint32_t u;
    asm("cvt.rna.tf32.f32 %0, %1;" : "=r"(u) : "f"(f));
    return u;
}

__device__ __forceinline__ void mma_tf32(float* c, const uint32_t* a, const uint32_t* b) {
    asm volatile(
        "mma.sync.aligned.m16n8k8.row.col.f32.tf32.tf32.f32 "
        "{%0,%1,%2,%3}, {%4,%5,%6,%7}, {%8,%9}, {%0,%1,%2,%3};\n"
        : "+f"(c[0]), "+f"(c[1]), "+f"(c[2]), "+f"(c[3])
        : "r"(a[0]), "r"(a[1]), "r"(a[2]), "r"(a[3]), "r"(b[0]), "r"(b[1]));
}

// fp16 mma m16n8k16, fp32 accum
__device__ __forceinline__ void mma_f16(float* c, const uint4& a, uint32_t b0, uint32_t b1) {
    asm volatile(
        "mma.sync.aligned.m16n8k16.row.col.f32.f16.f16.f32 "
        "{%0,%1,%2,%3}, {%4,%5,%6,%7}, {%8,%9}, {%0,%1,%2,%3};\n"
        : "+f"(c[0]), "+f"(c[1]), "+f"(c[2]), "+f"(c[3])
        : "r"(a.x), "r"(a.y), "r"(a.z), "r"(a.w), "r"(b0), "r"(b1));
}

__device__ __forceinline__ uint32_t pack2_f16(float e0, float e1) {
    __half2 t = __floats2half2_rn(e0, e1);  // .x = low half
    return *(uint32_t*)&t;
}

__device__ __forceinline__ float sigf(float x) {
    return 1.0f / (1.0f + __expf(-x));
}

// Warp-uniform wait on one producer slice (rare slow path).
__device__ __forceinline__ void wait_slice(unsigned& rmask, int s, int mt, unsigned need) {
    if (!((rmask >> s) & 1u)) {
        while ((int)(g_slot[mt][s][0] - need) < 0) { }
        __threadfence();
        rmask |= (1u << s);
    }
}

// Build fp16 B-fragments for a 48-col x 512-k weight tile with the GATE-LOCAL
// column order (n = wn*24 + gate*8 + jl -> row gate*H + j0 + wn*8 + jl).
// All 3 gates of a hidden unit land in the SAME C-fragment thread.
__device__ __forceinline__ void build_wfrag_f16(
    uint32_t* Wu, const float* __restrict__ Wsrc, int j0, int tid, int slot_off, int nthreads)
{
    for (int idx = tid; idx < 48 * 256; idx += nthreads) {
        int n  = idx >> 8;
        int k  = (idx & 255) << 1;
        int wn_t = n / 24;
        int rem  = n - wn_t * 24;
        int gate = rem >> 3, jl = rem & 7;
        const float* wrow = Wsrc + ((size_t)(gate * H_ + j0 + wn_t * 8 + jl)) * H_;
        uint32_t v = pack2_f16(wrow[k], wrow[k + 1]);
        int nt = (n >> 3) + slot_off;
        int ks = k >> 4, kr = k & 15;
        int rr = (kr >= 8) ? 1 : 0;
        int lw = (n & 7) * 4 + ((kr >> 1) & 3);
        Wu[(((nt * 32 + ks) * 32 + lw) << 1) + rr] = v;
    }
}

// ---------------------------------------------------------------------------
// tf32 tensor-core GEMM (phase 1): xg0 = x @ Wih0^T + bih0   (unchanged)
// ---------------------------------------------------------------------------
__global__ void __launch_bounds__(256) gemm_tf32_kernel(
    const float* __restrict__ A, const float* __restrict__ W,
    const float* __restrict__ bias, int K, float* __restrict__ C)
{
    __shared__ uint32_t As[128][36];
    __shared__ uint32_t Bs[128][36];

    const int tid  = threadIdx.x;
    const int m0   = blockIdx.y * 128;
    const int n0   = blockIdx.x * 128;
    const int warp = tid >> 5, lane = tid & 31;
    const int wm = warp >> 2, wn = warp & 3;
    const int g  = lane >> 2, tg = lane & 3;

    float acc[4][4][4] = {};

    for (int k0 = 0; k0 < K; k0 += 32) {
#pragma unroll
        for (int r = 0; r < 4; r++) {
            int f   = tid + (r << 8);
            int row = f >> 3;
            int c4  = (f & 7) << 2;
            float4 va = *(const float4*)(A + (size_t)(m0 + row) * K + k0 + c4);
            As[row][c4 + 0] = f2tf(va.x);
            As[row][c4 + 1] = f2tf(va.y);
            As[row][c4 + 2] = f2tf(va.z);
            As[row][c4 + 3] = f2tf(va.w);
            float4 vb = *(const float4*)(W + (size_t)(n0 + row) * K + k0 + c4);
            Bs[row][c4 + 0] = f2tf(vb.x);
            Bs[row][c4 + 1] = f2tf(vb.y);
            Bs[row][c4 + 2] = f2tf(vb.z);
            Bs[row][c4 + 3] = f2tf(vb.w);
        }
        __syncthreads();

#pragma unroll
        for (int s = 0; s < 4; s++) {
            const int kb = s << 3;
            uint32_t a[4][4], b[4][2];
#pragma unroll
            for (int i = 0; i < 4; i++) {
                int r0 = wm * 64 + i * 16 + g;
                a[i][0] = As[r0][kb + tg];
                a[i][1] = As[r0 + 8][kb + tg];
                a[i][2] = As[r0][kb + tg + 4];
                a[i][3] = As[r0 + 8][kb + tg + 4];
            }
#pragma unroll
            for (int jx = 0; jx < 4; jx++) {
                int c = wn * 32 + jx * 8 + g;
                b[jx][0] = Bs[c][kb + tg];
                b[jx][1] = Bs[c][kb + tg + 4];
            }
#pragma unroll
            for (int i = 0; i < 4; i++)
#pragma unroll
                for (int jx = 0; jx < 4; jx++)
                    mma_tf32(acc[i][jx], a[i], b[jx]);
        }
        __syncthreads();
    }

#pragma unroll
    for (int i = 0; i < 4; i++) {
        int r0 = m0 + wm * 64 + i * 16 + g;
#pragma unroll
        for (int jx = 0; jx < 4; jx++) {
            int col = n0 + wn * 32 + jx * 8 + tg * 2;
            float2 bv = *(const float2*)(bias + col);
            float2 o0 = make_float2(acc[i][jx][0] + bv.x, acc[i][jx][1] + bv.y);
            float2 o1 = make_float2(acc[i][jx][2] + bv.x, acc[i][jx][3] + bv.y);
            *(float2*)(C + (size_t)r0 * G3H + col)       = o0;
            *(float2*)(C + (size_t)(r0 + 8) * G3H + col) = o1;
        }
    }
}

// ---------------------------------------------------------------------------
// MERGED two-layer GRU with DATAFLOW SYNC (no full barrier). 257 windows:
//   warps 0-7  (task 0): h0(t)   = GRU0(h0(t-1), xg0[t])          [t < 256]
//   warps 8-15 (task 1): h1(t-1) = GRU1(h1(t-2), y0(t-1)=h0(t-1)) [t >= 1]
// Block (mt,jt) produces ks-slice jt of the A-frag arrays; consumers gate
// each ks iteration on that producer's published gen only. Consumption is
// rotated to start at the own slice. One flag sweep + ballot per warp per
// window; laggards handled by a rare spin. h-frag buffers are 4-deep; every
// storing warp has verified ALL producers >= t before its stores (WAR-safe).
// ---------------------------------------------------------------------------
__global__ void __launch_bounds__(512, 1) gru_merged_kernel(
    const float* __restrict__ Whh0, const float* __restrict__ bhh0,
    const float* __restrict__ Whh1, const float* __restrict__ bhh1,
    const float* __restrict__ Wih1, const float* __restrict__ bih1)
{
    extern __shared__ char smraw[];
    uint2* Wf = (uint2*)smraw;   // 18 slots: 0-5 Whh0, 6-11 Whh1, 12-17 Wih1

    const int tid = threadIdx.x;
    const int bid = blockIdx.x;
    const int jt = bid & 31, mt = bid >> 5;
    const int m0 = mt * 64, j0 = jt * 16;
    const int w = tid >> 5, lane = tid & 31;
    const int task = w >> 3, wsub = w & 7;
    const int wm = wsub >> 1, wn = wsub & 1;
    const int g = lane >> 2, tg = lane & 3;
    const int m16 = mt * 4 + wm;

    // base gen snapshot (own slot; only this block writes it; every block
    // publishes exactly 258 gens per launch so bases agree across blocks)
    const unsigned bgen = g_slot[mt][jt][0];

    build_wfrag_f16((uint32_t*)Wf, Whh0, j0, tid, 0, 512);
    build_wfrag_f16((uint32_t*)Wf, Whh1, j0, tid, 6, 512);
    build_wfrag_f16((uint32_t*)Wf, Wih1, j0, tid, 12, 512);

    // Zero h0frag buf0 (h0(-1), read at window 0) and h1frag buf1 (h1(-1),
    // read at window 1), group-local slices
    {
        int idx = (bid & 31) * 512 + tid;      // 0..16383
        size_t base = (size_t)mt * 4096;
        uint4 z = make_uint4(0, 0, 0, 0);
        if      (idx < 4096) g_h0frag[0][base + idx] = z;
        else if (idx < 8192) g_h1frag[1][base + idx - 4096] = z;
    }

    const int jc    = j0 + wn * 8 + 2 * tg;
    const int mrow0 = m0 + wm * 16 + g;
    const int mrow1 = mrow0 + 8;

    // biases
    float br0[2], bz0[2], bn0[2];             // task 0
    float Br1[2], Bz1[2], bxn1[2], bhn1[2];   // task 1
    if (task == 0) {
        br0[0] = bhh0[jc];          br0[1] = bhh0[jc + 1];
        bz0[0] = bhh0[H_ + jc];     bz0[1] = bhh0[H_ + jc + 1];
        bn0[0] = bhh0[2 * H_ + jc]; bn0[1] = bhh0[2 * H_ + jc + 1];
    } else {
#pragma unroll
        for (int c = 0; c < 2; c++) {
            Br1[c]  = bih1[jc + c] + bhh1[jc + c];
            Bz1[c]  = bih1[H_ + jc + c] + bhh1[H_ + jc + c];
            bxn1[c] = bih1[2 * H_ + jc + c];
            bhn1[c] = bhh1[2 * H_ + jc + c];
        }
    }

    float hreg[4] = {0.f, 0.f, 0.f, 0.f};
    float xr[4], xz[4], xn[4];

    auto prefetch_xg = [&](int tt) {
        size_t b0 = ((size_t)mrow0 * T_ + tt) * G3H + jc;
        size_t b1 = ((size_t)mrow1 * T_ + tt) * G3H + jc;
        float2 v;
        v = *(const float2*)(g_xg + b0);           xr[0] = v.x; xr[1] = v.y;
        v = *(const float2*)(g_xg + b0 + H_);      xz[0] = v.x; xz[1] = v.y;
        v = *(const float2*)(g_xg + b0 + 2 * H_);  xn[0] = v.x; xn[1] = v.y;
        v = *(const float2*)(g_xg + b1);           xr[2] = v.x; xr[3] = v.y;
        v = *(const float2*)(g_xg + b1 + H_);      xz[2] = v.x; xz[3] = v.y;
        v = *(const float2*)(g_xg + b1 + 2 * H_);  xn[2] = v.x; xn[3] = v.y;
    };
    if (task == 0) prefetch_xg(0);

    // init publish: zero-init + weights staged; gen = bgen + 1
    __syncthreads();
    if (tid == 0) { __threadfence(); g_slot[mt][jt][0] = bgen + 1u; }

    const size_t fbB = (size_t)(m16 * 32) * 32 + lane;      // + s*32 per slice
    const size_t sb  = ((size_t)(m16 * 32) + jt) * 32 + lane;

    for (int t = 0; t <= T_; t++) {
        const unsigned need = bgen + 1u + (unsigned)t;

        if (task == 0) {
            if (t < T_) {
                const uint4* __restrict__ A0 = g_h0frag[t & 3];
                float C[3][4] = {};

                // issue own slice immediately (no wait), then sweep flags
                uint4 b[4];
                b[0] = A0[fbB + (size_t)jt * 32];
                unsigned fl = g_slot[mt][lane][0];
                unsigned rmask = __ballot_sync(0xffffffffu, (int)(fl - need) >= 0)
                                 | (1u << jt);
                __threadfence();
#pragma unroll
                for (int p = 1; p < 4; p++) {
                    int s = (jt + p) & 31;
                    wait_slice(rmask, s, mt, need);
                    b[p] = A0[fbB + (size_t)s * 32];
                }
#pragma unroll 4
                for (int i = 0; i < 32; i++) {
                    int s = (jt + i) & 31;
                    uint4 a = b[i & 3];
                    if (i + 4 < 32) {
                        int s4 = (jt + i + 4) & 31;
                        wait_slice(rmask, s4, mt, need);
                        b[i & 3] = A0[fbB + (size_t)s4 * 32];
                    }
#pragma unroll
                    for (int nt = 0; nt < 3; nt++) {
                        uint2 wv = Wf[((wn * 3 + nt) * 32 + s) * 32 + lane];
                        mma_f16(C[nt], a, wv.x, wv.y);
                    }
                }

                float hv[4];
#pragma unroll
                for (int i = 0; i < 4; i++) {
                    float r  = sigf(xr[i] + C[0][i] + br0[i & 1]);
                    float z  = sigf(xz[i] + C[1][i] + bz0[i & 1]);
                    float nv = tanhf(xn[i] + r * (C[2][i] + bn0[i & 1]));
                    float h  = (1.0f - z) * nv + z * hreg[i];
                    hreg[i] = h; hv[i] = h;
                }
                uint2 hiu = make_uint2(pack2_f16(hv[0], hv[1]), pack2_f16(hv[2], hv[3]));
                ((uint2*)&g_h0frag[(t + 1) & 3][sb])[wn] = hiu;

                if (t < T_ - 1) prefetch_xg(t + 1);
            }
        } else if (t >= 1) {
            const uint4* __restrict__ A0 = g_h0frag[t & 3];
            const uint4* __restrict__ A1 = g_h1frag[t & 3];

            float Cri[4] = {}, Crh[4] = {}, Czi[4] = {}, Czh[4] = {};
            float Cni[4] = {}, Cnh[4] = {};

            uint4 a0b[4], a1b[4];
            a0b[0] = A0[fbB + (size_t)jt * 32];
            a1b[0] = A1[fbB + (size_t)jt * 32];
            unsigned fl = g_slot[mt][lane][0];
            unsigned rmask = __ballot_sync(0xffffffffu, (int)(fl - need) >= 0)
                             | (1u << jt);
            __threadfence();
#pragma unroll
            for (int p = 1; p < 4; p++) {
                int s = (jt + p) & 31;
                wait_slice(rmask, s, mt, need);
                a0b[p] = A0[fbB + (size_t)s * 32];
                a1b[p] = A1[fbB + (size_t)s * 32];
            }

#pragma unroll 4
            for (int i = 0; i < 32; i++) {
                int s = (jt + i) & 31;
                uint4 a0 = a0b[i & 3], a1 = a1b[i & 3];
                if (i + 4 < 32) {
                    int s4 = (jt + i + 4) & 31;
                    wait_slice(rmask, s4, mt, need);
                    a0b[i & 3] = A0[fbB + (size_t)s4 * 32];
                    a1b[i & 3] = A1[fbB + (size_t)s4 * 32];
                }
                // hh-side (Whh1, slots 6..11) against h1(t-2)
                uint2 wh0 = Wf[((6 + wn * 3 + 0) * 32 + s) * 32 + lane];
                mma_f16(Crh, a1, wh0.x, wh0.y);
                uint2 wh1 = Wf[((6 + wn * 3 + 1) * 32 + s) * 32 + lane];
                mma_f16(Czh, a1, wh1.x, wh1.y);
                uint2 wh2 = Wf[((6 + wn * 3 + 2) * 32 + s) * 32 + lane];
                mma_f16(Cnh, a1, wh2.x, wh2.y);
                // ih-side (Wih1, slots 12..17) against h0(t-1)
                uint2 wi0 = Wf[((12 + wn * 3 + 0) * 32 + s) * 32 + lane];
                mma_f16(Cri, a0, wi0.x, wi0.y);
                uint2 wi1 = Wf[((12 + wn * 3 + 1) * 32 + s) * 32 + lane];
                mma_f16(Czi, a0, wi1.x, wi1.y);
                uint2 wi2 = Wf[((12 + wn * 3 + 2) * 32 + s) * 32 + lane];
                mma_f16(Cni, a0, wi2.x, wi2.y);
            }

            float hv[4];
#pragma unroll
            for (int i = 0; i < 4; i++) {
                float r  = sigf(Cri[i] + Crh[i] + Br1[i & 1]);
                float z  = sigf(Czi[i] + Czh[i] + Bz1[i & 1]);
                float nv = tanhf(Cni[i] + bxn1[i & 1] + r * (Cnh[i] + bhn1[i & 1]));
                float h  = (1.0f - z) * nv + z * hreg[i];
                hreg[i] = h; hv[i] = h;
            }
            if (t == T_) {
                *(float2*)(g_hT + (size_t)mrow0 * H_ + jc) = make_float2(hv[0], hv[1]);
                *(float2*)(g_hT + (size_t)mrow1 * H_ + jc) = make_float2(hv[2], hv[3]);
            } else {
                uint2 hiu = make_uint2(pack2_f16(hv[0], hv[1]), pack2_f16(hv[2], hv[3]));
                ((uint2*)&g_h1frag[(t + 1) & 3][sb])[wn] = hiu;
            }
        }

        // publish completion of window t (covers h0 and h1 slice stores)
        __syncthreads();
        if (tid == 0) { __threadfence(); g_slot[mt][jt][0] = bgen + 2u + (unsigned)t; }
    }
}

// ---------------------------------------------------------------------------
// Head: out = relu(relu(hT) @ fc1^T + b1) @ fc2^T + b2
// ---------------------------------------------------------------------------
__global__ void __launch_bounds__(512) head_kernel(
    const float* __restrict__ w1, const float* __restrict__ b1,
    const float* __restrict__ w2, const float* __restrict__ b2,
    float* __restrict__ out)
{
    __shared__ float sh[H_];
    __shared__ float s1[128];
    const int b = blockIdx.x;
    const int tid = threadIdx.x;
    const int w = tid >> 5, lane = tid & 31;

    sh[tid] = fmaxf(g_hT[(size_t)b * H_ + tid], 0.0f);
    __syncthreads();

#pragma unroll
    for (int oo = 0; oo < 8; oo++) {
        int o = w * 8 + oo;
        const float* wr = w1 + (size_t)o * H_;
        float acc = 0.f;
#pragma unroll
        for (int c = 0; c < 4; c++) {
            int k = c * 128 + lane * 4;
            float4 wv = *(const float4*)(wr + k);
            float4 hv = *(const float4*)(&sh[k]);
            acc += wv.x * hv.x + wv.y * hv.y + wv.z * hv.z + wv.w * hv.w;
        }
#pragma unroll
        for (int off = 16; off; off >>= 1)
            acc += __shfl_down_sync(0xFFFFFFFFu, acc, off);
        if (lane == 0) s1[o] = fmaxf(acc + b1[o], 0.0f);
    }
    __syncthreads();

    if (w < 10) {
        const float* wr = w2 + (size_t)w * 128;
        float acc = 0.f;
#pragma unroll
        for (int c = 0; c < 4; c++) {
            int k = lane + c * 32;
            acc += s1[k] * wr[k];
        }
#pragma unroll
        for (int off = 16; off; off >>= 1)
            acc += __shfl_down_sync(0xFFFFFFFFu, acc, off);
        if (lane == 0) out[(size_t)b * 10 + w] = acc + b2[w];
    }
}

// ---------------------------------------------------------------------------
// Launch
// ---------------------------------------------------------------------------
extern "C" void kernel_launch(void* const* d_in, const int* in_sizes, int n_in,
                              void* d_out, int out_size)
{
    const float* x    = (const float*)d_in[0];
    const float* Wih0 = (const float*)d_in[1];
    const float* Whh0 = (const float*)d_in[2];
    const float* bih0 = (const float*)d_in[3];
    const float* bhh0 = (const float*)d_in[4];
    const float* Wih1 = (const float*)d_in[5];
    const float* Whh1 = (const float*)d_in[6];
    const float* bih1 = (const float*)d_in[7];
    const float* bhh1 = (const float*)d_in[8];
    const float* fc1w = (const float*)d_in[9];
    const float* fc1b = (const float*)d_in[10];
    const float* fc2w = (const float*)d_in[11];
    const float* fc2b = (const float*)d_in[12];
    float* out = (float*)d_out;

    float* xg_ptr = nullptr;
    cudaGetSymbolAddress((void**)&xg_ptr, g_xg);

    const int merged_smem = 18 * 32 * 32 * 8;   // 144KB
    cudaFuncSetAttribute((const void*)gru_merged_kernel,
                         cudaFuncAttributeMaxDynamicSharedMemorySize, merged_smem);

    dim3 gemm_grid(G3H / 128, BT / 128);  // (12, 512)

    // Phase 1: xg0 = x @ W_ih0^T + b_ih0   (K = 128)
    gemm_tf32_kernel<<<gemm_grid, 256>>>(x, Wih0, bih0, D_, xg_ptr);

    // Phase 2: merged two-layer GRU (257 dataflow-synced windows)
    gru_merged_kernel<<<128, 512, merged_smem>>>(Whh0, bhh0, Whh1, bhh1, Wih1, bih1);

    // Phase 3: MLP head
    head_kernel<<<B_, 512>>>(fc1w, fc1b, fc2w, fc2b, out);
}

// round 17
// speedup vs baseline: 3.1707x; 3.1707x over previous
#include <cuda_runtime.h>
#include <cuda_fp16.h>
#include <math.h>
#include <stdint.h>

// Problem dims (fixed by the dataset)
#define B_   256
#define T_   256
#define D_   128
#define H_   512
#define G3H  1536
#define BT   (B_ * T_)

// ---------------------------------------------------------------------------
// Scratch (static device allocations; harness forbids cudaMalloc)
// ---------------------------------------------------------------------------
__device__ float g_xg[(size_t)BT * G3H];   // xg0 (layer-0 input projections)
__device__ float g_hT[B_ * H_];            // final hidden of layer 1
// h fragments, A-layout, fp16 single, double buffered
__device__ uint4 g_h0frag[2][16 * 32 * 32];
__device__ uint4 g_h1frag[2][16 * 32 * 32];

// Slot barrier: each block owns one 128B line; monotonic gens, snapshot at
// kernel start (only the owner writes its slot; all blocks of a group store
// the same number of gens per kernel) -> replay-safe.
__device__ volatile unsigned g_slot[4][32][32];

__device__ __forceinline__ void slot_barrier(int grp, int blk, unsigned gen) {
    __syncthreads();
    if (threadIdx.x == 0) {
        __threadfence();                    // release own writes
        g_slot[grp][blk][0] = gen;
    }
    if (threadIdx.x < 32) {
        while ((int)(g_slot[grp][threadIdx.x][0] - gen) < 0) { }
        __threadfence();                    // acquire
    }
    __syncthreads();
}

// ---------------------------------------------------------------------------
// math helpers
// ---------------------------------------------------------------------------
// fp16 mma m16n8k16, fp32 accum
__device__ __forceinline__ void mma_f16(float* c, const uint4& a, uint32_t b0, uint32_t b1) {
    asm volatile(
        "mma.sync.aligned.m16n8k16.row.col.f32.f16.f16.f32 "
        "{%0,%1,%2,%3}, {%4,%5,%6,%7}, {%8,%9}, {%0,%1,%2,%3};\n"
        : "+f"(c[0]), "+f"(c[1]), "+f"(c[2]), "+f"(c[3])
        : "r"(a.x), "r"(a.y), "r"(a.z), "r"(a.w), "r"(b0), "r"(b1));
}

__device__ __forceinline__ uint32_t pack2_f16(float e0, float e1) {
    __half2 t = __floats2half2_rn(e0, e1);  // .x = low half
    return *(uint32_t*)&t;
}

__device__ __forceinline__ float sigf(float x) {
    return 1.0f / (1.0f + __expf(-x));
}

// Build fp16 B-fragments for a 48-col x 512-k weight tile with the GATE-LOCAL
// column order (n = wn*24 + gate*8 + jl -> row gate*H + j0 + wn*8 + jl).
// All 3 gates of a hidden unit land in the SAME C-fragment thread.
__device__ __forceinline__ void build_wfrag_f16(
    uint32_t* Wu, const float* __restrict__ Wsrc, int j0, int tid, int slot_off, int nthreads)
{
    for (int idx = tid; idx < 48 * 256; idx += nthreads) {
        int n  = idx >> 8;
        int k  = (idx & 255) << 1;
        int wn_t = n / 24;
        int rem  = n - wn_t * 24;
        int gate = rem >> 3, jl = rem & 7;
        const float* wrow = Wsrc + ((size_t)(gate * H_ + j0 + wn_t * 8 + jl)) * H_;
        uint32_t v = pack2_f16(wrow[k], wrow[k + 1]);
        int nt = (n >> 3) + slot_off;
        int ks = k >> 4, kr = k & 15;
        int rr = (kr >= 8) ? 1 : 0;
        int lw = (n & 7) * 4 + ((kr >> 1) & 3);
        Wu[(((nt * 32 + ks) * 32 + lw) << 1) + rr] = v;
    }
}

// ---------------------------------------------------------------------------
// fp16 tensor-core GEMM (phase 1): xg0 = x @ Wih0^T + bih0
// Block tile 128(M) x 128(N) x 32(K), 8 warps (2x4), warp tile 64x32,
// m16n8k16: 2 k-steps per K-chunk, half the MMA count of the tf32 version.
// ---------------------------------------------------------------------------
__global__ void __launch_bounds__(256) gemm_f16_kernel(
    const float* __restrict__ A, const float* __restrict__ W,
    const float* __restrict__ bias, int K, float* __restrict__ C)
{
    __shared__ uint32_t As[128][20];   // 16 half2 k-pairs + pad
    __shared__ uint32_t Bs[128][20];

    const int tid  = threadIdx.x;
    const int m0   = blockIdx.y * 128;
    const int n0   = blockIdx.x * 128;
    const int warp = tid >> 5, lane = tid & 31;
    const int wm = warp >> 2, wn = warp & 3;
    const int g  = lane >> 2, tg = lane & 3;

    float acc[4][4][4] = {};

    for (int k0 = 0; k0 < K; k0 += 32) {
#pragma unroll
        for (int r = 0; r < 4; r++) {
            int f   = tid + (r << 8);
            int row = f >> 3;
            int c4  = (f & 7) << 2;        // float offset; pair offset = c4>>1
            float4 va = *(const float4*)(A + (size_t)(m0 + row) * K + k0 + c4);
            As[row][(c4 >> 1)]     = pack2_f16(va.x, va.y);
            As[row][(c4 >> 1) + 1] = pack2_f16(va.z, va.w);
            float4 vb = *(const float4*)(W + (size_t)(n0 + row) * K + k0 + c4);
            Bs[row][(c4 >> 1)]     = pack2_f16(vb.x, vb.y);
            Bs[row][(c4 >> 1) + 1] = pack2_f16(vb.z, vb.w);
        }
        __syncthreads();

#pragma unroll
        for (int s = 0; s < 2; s++) {
            const int kb = s << 3;        // pair offset of this k16 step
            uint4 a[4];
            uint32_t b[4][2];
#pragma unroll
            for (int i = 0; i < 4; i++) {
                int r0 = wm * 64 + i * 16 + g;
                a[i].x = As[r0][kb + tg];
                a[i].y = As[r0 + 8][kb + tg];
                a[i].z = As[r0][kb + tg + 4];
                a[i].w = As[r0 + 8][kb + tg + 4];
            }
#pragma unroll
            for (int jx = 0; jx < 4; jx++) {
                int c = wn * 32 + jx * 8 + g;
                b[jx][0] = Bs[c][kb + tg];
                b[jx][1] = Bs[c][kb + tg + 4];
            }
#pragma unroll
            for (int i = 0; i < 4; i++)
#pragma unroll
                for (int jx = 0; jx < 4; jx++)
                    mma_f16(acc[i][jx], a[i], b[jx][0], b[jx][1]);
        }
        __syncthreads();
    }

#pragma unroll
    for (int i = 0; i < 4; i++) {
        int r0 = m0 + wm * 64 + i * 16 + g;
#pragma unroll
        for (int jx = 0; jx < 4; jx++) {
            int col = n0 + wn * 32 + jx * 8 + tg * 2;
            float2 bv = *(const float2*)(bias + col);
            float2 o0 = make_float2(acc[i][jx][0] + bv.x, acc[i][jx][1] + bv.y);
            float2 o1 = make_float2(acc[i][jx][2] + bv.x, acc[i][jx][3] + bv.y);
            *(float2*)(C + (size_t)r0 * G3H + col)       = o0;
            *(float2*)(C + (size_t)(r0 + 8) * G3H + col) = o1;
        }
    }
}

// ---------------------------------------------------------------------------
// MERGED two-layer GRU (round-15 kernel, byte-identical). 257 windows:
//   warps 0-7  (task 0): h0(t)   = GRU0(h0(t-1), xg0[t])          [t < 256]
//   warps 8-15 (task 1): h1(t-1) = GRU1(h1(t-2), y0(t-1)=h0(t-1)) [t >= 1]
// smem: Whh0|Whh1|Wih1 fp16 frags = 144KB. Per-iteration L2 streams: task0 A0
// (8-outstanding ring), task1 A0+A1 (4-deep rings each).
// ---------------------------------------------------------------------------
__global__ void __launch_bounds__(512, 1) gru_merged_kernel(
    const float* __restrict__ Whh0, const float* __restrict__ bhh0,
    const float* __restrict__ Whh1, const float* __restrict__ bhh1,
    const float* __restrict__ Wih1, const float* __restrict__ bih1)
{
    extern __shared__ char smraw[];
    uint2* Wf = (uint2*)smraw;   // 18 slots: 0-5 Whh0, 6-11 Whh1, 12-17 Wih1

    const int tid = threadIdx.x;
    const int bid = blockIdx.x;
    const int jt = bid & 31, mt = bid >> 5;
    const int m0 = mt * 64, j0 = jt * 16;
    const int w = tid >> 5, lane = tid & 31;
    const int task = w >> 3, wsub = w & 7;
    const int wm = wsub >> 1, wn = wsub & 1;
    const int g = lane >> 2, tg = lane & 3;
    const int m16 = mt * 4 + wm;

    unsigned bgen = 0;
    if (tid < 32) bgen = g_slot[mt][jt][0];
    unsigned genc = 0;

    build_wfrag_f16((uint32_t*)Wf, Whh0, j0, tid, 0, 512);
    build_wfrag_f16((uint32_t*)Wf, Whh1, j0, tid, 6, 512);
    build_wfrag_f16((uint32_t*)Wf, Wih1, j0, tid, 12, 512);

    // Zero h0frag buf0 (h0(-1)) and h1frag buf1 (h1(-1)), group-local slices
    {
        int idx = (bid & 31) * 512 + tid;      // 0..16383
        size_t base = (size_t)mt * 4096;
        uint4 z = make_uint4(0, 0, 0, 0);
        if      (idx < 4096) g_h0frag[0][base + idx] = z;
        else if (idx < 8192) g_h1frag[1][base + idx - 4096] = z;
    }

    const int jc    = j0 + wn * 8 + 2 * tg;   // this thread's first j column
    const int mrow0 = m0 + wm * 16 + g;       // this thread's rows
    const int mrow1 = mrow0 + 8;

    // biases
    float br0[2], bz0[2], bn0[2];             // task 0
    float Br1[2], Bz1[2], bxn1[2], bhn1[2];   // task 1
    if (task == 0) {
        br0[0] = bhh0[jc];          br0[1] = bhh0[jc + 1];
        bz0[0] = bhh0[H_ + jc];     bz0[1] = bhh0[H_ + jc + 1];
        bn0[0] = bhh0[2 * H_ + jc]; bn0[1] = bhh0[2 * H_ + jc + 1];
    } else {
#pragma unroll
        for (int c = 0; c < 2; c++) {
            Br1[c]  = bih1[jc + c] + bhh1[jc + c];
            Bz1[c]  = bih1[H_ + jc + c] + bhh1[H_ + jc + c];
            bxn1[c] = bih1[2 * H_ + jc + c];
            bhn1[c] = bhh1[2 * H_ + jc + c];
        }
    }

    float hreg[4] = {0.f, 0.f, 0.f, 0.f};
    float xr[4], xz[4], xn[4];

    auto prefetch_xg = [&](int tt) {
        size_t b0 = ((size_t)mrow0 * T_ + tt) * G3H + jc;
        size_t b1 = ((size_t)mrow1 * T_ + tt) * G3H + jc;
        float2 v;
        v = *(const float2*)(g_xg + b0);           xr[0] = v.x; xr[1] = v.y;
        v = *(const float2*)(g_xg + b0 + H_);      xz[0] = v.x; xz[1] = v.y;
        v = *(const float2*)(g_xg + b0 + 2 * H_);  xn[0] = v.x; xn[1] = v.y;
        v = *(const float2*)(g_xg + b1);           xr[2] = v.x; xr[3] = v.y;
        v = *(const float2*)(g_xg + b1 + H_);      xz[2] = v.x; xz[3] = v.y;
        v = *(const float2*)(g_xg + b1 + 2 * H_);  xn[2] = v.x; xn[3] = v.y;
    };
    if (task == 0) prefetch_xg(0);

    slot_barrier(mt, jt, bgen + (++genc));

    const size_t fb0 = (size_t)(m16 * 32) * 32 + lane;
    const size_t sb  = ((size_t)(m16 * 32) + jt) * 32 + lane;

    for (int t = 0; t <= T_; t++) {
        if (task == 0) {
            if (t < T_) {
                const uint4* __restrict__ A0 = g_h0frag[t & 1];
                float Ca[3][4] = {}, Cb[3][4] = {};

                // 4-pair-deep ring: 8 outstanding loads, lookahead 8 ks
                uint4 buf[4][2];
#pragma unroll
                for (int p = 0; p < 4; p++) {
                    buf[p][0] = A0[fb0 + (2 * p) * 32];
                    buf[p][1] = A0[fb0 + (2 * p + 1) * 32];
                }
#pragma unroll 4
                for (int kp = 0; kp < 16; kp++) {
                    const int pb = kp & 3;
                    uint4 a0 = buf[pb][0], a1 = buf[pb][1];
                    if (kp + 4 < 16) {
                        buf[pb][0] = A0[fb0 + (2 * kp + 8) * 32];
                        buf[pb][1] = A0[fb0 + (2 * kp + 9) * 32];
                    }
#pragma unroll
                    for (int nt = 0; nt < 3; nt++) {
                        uint2 w0 = Wf[((wn * 3 + nt) * 32 + 2 * kp) * 32 + lane];
                        mma_f16(Ca[nt], a0, w0.x, w0.y);
                        uint2 w1 = Wf[((wn * 3 + nt) * 32 + 2 * kp + 1) * 32 + lane];
                        mma_f16(Cb[nt], a1, w1.x, w1.y);
                    }
                }

                float hv[4];
#pragma unroll
                for (int i = 0; i < 4; i++) {
                    float cr = Ca[0][i] + Cb[0][i];
                    float cz = Ca[1][i] + Cb[1][i];
                    float cn = Ca[2][i] + Cb[2][i];
                    float r  = sigf(xr[i] + cr + br0[i & 1]);
                    float z  = sigf(xz[i] + cz + bz0[i & 1]);
                    float nv = tanhf(xn[i] + r * (cn + bn0[i & 1]));
                    float h  = (1.0f - z) * nv + z * hreg[i];
                    hreg[i] = h; hv[i] = h;
                }
                uint2 hiu = make_uint2(pack2_f16(hv[0], hv[1]), pack2_f16(hv[2], hv[3]));
                const int nb = (t + 1) & 1;
                ((uint2*)&g_h0frag[nb][sb])[wn] = hiu;

                if (t < T_ - 1) prefetch_xg(t + 1);
            }
        } else if (t >= 1) {
            const uint4* __restrict__ A0 = g_h0frag[t & 1];
            const uint4* __restrict__ A1 = g_h1frag[t & 1];

            // 6 independent accumulator chains: {r,z,n} x {ih, hh}
            float Cri[4] = {}, Crh[4] = {}, Czi[4] = {}, Czh[4] = {};
            float Cni[4] = {}, Cnh[4] = {};

            // 4-deep ring prefetch on both A streams
            uint4 a0b[4], a1b[4];
#pragma unroll
            for (int p = 0; p < 4; p++) {
                a0b[p] = A0[fb0 + p * 32];
                a1b[p] = A1[fb0 + p * 32];
            }

#pragma unroll 4
            for (int ks = 0; ks < 32; ks++) {
                const int pb = ks & 3;
                uint4 a0 = a0b[pb], a1 = a1b[pb];
                if (ks + 4 < 32) {
                    size_t nf = fb0 + (ks + 4) * 32;
                    a0b[pb] = A0[nf];
                    a1b[pb] = A1[nf];
                }
                // hh-side (Whh1, smem slots 6..11) against h1(t-2)
                uint2 wh0 = Wf[((6 + wn * 3 + 0) * 32 + ks) * 32 + lane];
                mma_f16(Crh, a1, wh0.x, wh0.y);
                uint2 wh1 = Wf[((6 + wn * 3 + 1) * 32 + ks) * 32 + lane];
                mma_f16(Czh, a1, wh1.x, wh1.y);
                uint2 wh2 = Wf[((6 + wn * 3 + 2) * 32 + ks) * 32 + lane];
                mma_f16(Cnh, a1, wh2.x, wh2.y);
                // ih-side (Wih1, smem slots 12..17) against h0(t-1)
                uint2 wi0 = Wf[((12 + wn * 3 + 0) * 32 + ks) * 32 + lane];
                mma_f16(Cri, a0, wi0.x, wi0.y);
                uint2 wi1 = Wf[((12 + wn * 3 + 1) * 32 + ks) * 32 + lane];
                mma_f16(Czi, a0, wi1.x, wi1.y);
                uint2 wi2 = Wf[((12 + wn * 3 + 2) * 32 + ks) * 32 + lane];
                mma_f16(Cni, a0, wi2.x, wi2.y);
            }

            float hv[4];
#pragma unroll
            for (int i = 0; i < 4; i++) {
                float r  = sigf(Cri[i] + Crh[i] + Br1[i & 1]);
                float z  = sigf(Czi[i] + Czh[i] + Bz1[i & 1]);
                float nv = tanhf(Cni[i] + bxn1[i & 1] + r * (Cnh[i] + bhn1[i & 1]));
                float h  = (1.0f - z) * nv + z * hreg[i];
                hreg[i] = h; hv[i] = h;
            }
            if (t == T_) {
                *(float2*)(g_hT + (size_t)mrow0 * H_ + jc) = make_float2(hv[0], hv[1]);
                *(float2*)(g_hT + (size_t)mrow1 * H_ + jc) = make_float2(hv[2], hv[3]);
            } else {
                uint2 hiu = make_uint2(pack2_f16(hv[0], hv[1]), pack2_f16(hv[2], hv[3]));
                const int nb = (t + 1) & 1;
                ((uint2*)&g_h1frag[nb][sb])[wn] = hiu;
            }
        }

        slot_barrier(mt, jt, bgen + (++genc));
    }
}

// ---------------------------------------------------------------------------
// Head: out = relu(relu(hT) @ fc1^T + b1) @ fc2^T + b2
// ---------------------------------------------------------------------------
__global__ void __launch_bounds__(512) head_kernel(
    const float* __restrict__ w1, const float* __restrict__ b1,
    const float* __restrict__ w2, const float* __restrict__ b2,
    float* __restrict__ out)
{
    __shared__ float sh[H_];
    __shared__ float s1[128];
    const int b = blockIdx.x;
    const int tid = threadIdx.x;
    const int w = tid >> 5, lane = tid & 31;

    sh[tid] = fmaxf(g_hT[(size_t)b * H_ + tid], 0.0f);
    __syncthreads();

#pragma unroll
    for (int oo = 0; oo < 8; oo++) {
        int o = w * 8 + oo;
        const float* wr = w1 + (size_t)o * H_;
        float acc = 0.f;
#pragma unroll
        for (int c = 0; c < 4; c++) {
            int k = c * 128 + lane * 4;
            float4 wv = *(const float4*)(wr + k);
            float4 hv = *(const float4*)(&sh[k]);
            acc += wv.x * hv.x + wv.y * hv.y + wv.z * hv.z + wv.w * hv.w;
        }
#pragma unroll
        for (int off = 16; off; off >>= 1)
            acc += __shfl_down_sync(0xFFFFFFFFu, acc, off);
        if (lane == 0) s1[o] = fmaxf(acc + b1[o], 0.0f);
    }
    __syncthreads();

    if (w < 10) {
        const float* wr = w2 + (size_t)w * 128;
        float acc = 0.f;
#pragma unroll
        for (int c = 0; c < 4; c++) {
            int k = lane + c * 32;
            acc += s1[k] * wr[k];
        }
#pragma unroll
        for (int off = 16; off; off >>= 1)
            acc += __shfl_down_sync(0xFFFFFFFFu, acc, off);
        if (lane == 0) out[(size_t)b * 10 + w] = acc + b2[w];
    }
}

// ---------------------------------------------------------------------------
// Launch
// ---------------------------------------------------------------------------
extern "C" void kernel_launch(void* const* d_in, const int* in_sizes, int n_in,
                              void* d_out, int out_size)
{
    const float* x    = (const float*)d_in[0];
    const float* Wih0 = (const float*)d_in[1];
    const float* Whh0 = (const float*)d_in[2];
    const float* bih0 = (const float*)d_in[3];
    const float* bhh0 = (const float*)d_in[4];
    const float* Wih1 = (const float*)d_in[5];
    const float* Whh1 = (const float*)d_in[6];
    const float* bih1 = (const float*)d_in[7];
    const float* bhh1 = (const float*)d_in[8];
    const float* fc1w = (const float*)d_in[9];
    const float* fc1b = (const float*)d_in[10];
    const float* fc2w = (const float*)d_in[11];
    const float* fc2b = (const float*)d_in[12];
    float* out = (float*)d_out;

    float* xg_ptr = nullptr;
    cudaGetSymbolAddress((void**)&xg_ptr, g_xg);

    const int merged_smem = 18 * 32 * 32 * 8;   // 144KB
    cudaFuncSetAttribute((const void*)gru_merged_kernel,
                         cudaFuncAttributeMaxDynamicSharedMemorySize, merged_smem);

    dim3 gemm_grid(G3H / 128, BT / 128);  // (12, 512)

    // Phase 1: xg0 = x @ W_ih0^T + b_ih0   (K = 128, fp16 MMA)
    gemm_f16_kernel<<<gemm_grid, 256>>>(x, Wih0, bih0, D_, xg_ptr);

    // Phase 2: merged two-layer GRU (257 barrier windows)
    gru_merged_kernel<<<128, 512, merged_smem>>>(Whh0, bhh0, Whh1, bhh1, Wih1, bih1);

    // Phase 3: MLP head
    head_kernel<<<B_, 512>>>(fc1w, fc1b, fc2w, fc2b, out);
}